// round 12
// baseline (speedup 1.0000x reference)
#include <cuda_runtime.h>

#define N     2048
#define FIN   512
#define F     64
#define NT    32            // 64-row tiles per dimension
#define NTRI  528           // NT*(NT+1)/2

typedef unsigned long long u64;

// ---------------- scratch (static device allocations only) ----------------
__device__ float g_hpart[4][N * F];          // 2 MB: split-K partials of x@W
__device__ float g_h[N * F];                 // 512 KB
__device__ float g_rowsum[N];
__device__ int   g_cnt[NT];                  // completion counters per row-block
__device__ float g_opart[NT][N * F];         // 16 MB: slot = other tile index

#define ABS2MASK 0x7FFFFFFF7FFFFFFFULL

__device__ __forceinline__ u64 f2add(u64 a, u64 b) {
    u64 r; asm("add.rn.f32x2 %0, %1, %2;" : "=l"(r) : "l"(a), "l"(b)); return r;
}
__device__ __forceinline__ u64 f2fma(u64 a, u64 b, u64 c) {
    u64 r; asm("fma.rn.f32x2 %0, %1, %2, %3;" : "=l"(r) : "l"(a), "l"(b), "l"(c)); return r;
}
__device__ __forceinline__ u64 dupf(float x) {
    u64 r; unsigned u = __float_as_uint(x);
    asm("mov.b64 %0, {%1,%1};" : "=l"(r) : "r"(u)); return r;
}
__device__ __forceinline__ float unpack_sum(u64 v) {
    float lo, hi;
    asm("mov.b64 {%0,%1}, %2;" : "=f"(lo), "=f"(hi) : "l"(v));
    return lo + hi;
}
__device__ __forceinline__ void unpack2(u64 v, float& lo, float& hi) {
    asm("mov.b64 {%0,%1}, %2;" : "=f"(lo), "=f"(hi) : "l"(v));
}

#define FMA4(a, s, v) { (a).x += (s)*(v).x; (a).y += (s)*(v).y; (a).z += (s)*(v).z; (a).w += (s)*(v).w; }

// ---------------- K1: split-K GEMM partials ---------------------------------
__global__ __launch_bounds__(256) void k1_gemm_part(const float* __restrict__ x,
                                                    const float* __restrict__ W) {
    __shared__ float xs[16][128];   // 8 KB
    __shared__ float ws[32][F];     // 8 KB
    int tid = threadIdx.x;
    int r0 = blockIdx.x * 16;
    int ks = blockIdx.y;
    int kbase = ks * 128;

    // stage x tile [16][128]
#pragma unroll
    for (int u = 0; u < 2; u++) {
        int v = tid + u * 256;
        int r = v >> 5, c = v & 31;
        *(float4*)&xs[r][c * 4] =
            *(const float4*)&x[(size_t)(r0 + r) * FIN + kbase + c * 4];
    }

    int tx = tid & 15;
    int ty = tid >> 4;
    float4 acc[4];
#pragma unroll
    for (int q = 0; q < 4; q++) acc[q] = make_float4(0.f, 0.f, 0.f, 0.f);

#pragma unroll
    for (int kt = 0; kt < 128; kt += 32) {
        __syncthreads();
        // stage W tile [32][64]
#pragma unroll
        for (int u = 0; u < 2; u++) {
            int v = tid + u * 256;
            int r = v >> 4, c = v & 15;
            *(float4*)&ws[r][c * 4] =
                *(const float4*)&W[(size_t)(kbase + kt + r) * F + c * 4];
        }
        __syncthreads();
#pragma unroll
        for (int k4 = 0; k4 < 8; k4++) {
            float4 xv = *(const float4*)&xs[ty][kt + k4 * 4];
            float4 w0 = ((const float4*)&ws[k4 * 4 + 0][0])[tx];
            float4 w1 = ((const float4*)&ws[k4 * 4 + 1][0])[tx];
            float4 w2 = ((const float4*)&ws[k4 * 4 + 2][0])[tx];
            float4 w3 = ((const float4*)&ws[k4 * 4 + 3][0])[tx];
            FMA4(acc[0], xv.x, w0); FMA4(acc[1], xv.y, w1);
            FMA4(acc[2], xv.z, w2); FMA4(acc[3], xv.w, w3);
        }
    }
    float4 r;
    r.x = (acc[0].x + acc[1].x) + (acc[2].x + acc[3].x);
    r.y = (acc[0].y + acc[1].y) + (acc[2].y + acc[3].y);
    r.z = (acc[0].z + acc[1].z) + (acc[2].z + acc[3].z);
    r.w = (acc[0].w + acc[1].w) + (acc[2].w + acc[3].w);
    *(float4*)&g_hpart[ks][(size_t)(r0 + ty) * F + tx * 4] = r;
}

// ---------------- K1b: g_h = sum of 4 partials; zero rowsum + counters -----
__global__ __launch_bounds__(256) void k1b_reduce() {
    int idx = blockIdx.x * 256 + threadIdx.x;   // 128 x 256 = 32768 float4s
    float4 a0 = ((const float4*)g_hpart[0])[idx];
    float4 a1 = ((const float4*)g_hpart[1])[idx];
    float4 a2 = ((const float4*)g_hpart[2])[idx];
    float4 a3 = ((const float4*)g_hpart[3])[idx];
    float4 r;
    r.x = (a0.x + a1.x) + (a2.x + a3.x);
    r.y = (a0.y + a1.y) + (a2.y + a3.y);
    r.z = (a0.z + a1.z) + (a2.z + a3.z);
    r.w = (a0.w + a1.w) + (a2.w + a3.w);
    ((float4*)g_h)[idx] = r;
    if (idx < N) g_rowsum[idx] = 0.0f;
    if (idx < NT) g_cnt[idx] = 0;
}

// ---------------- tail reduction: out rows of one 64-row block -------------
__device__ __forceinline__ void reduce_rowblock(int r, float* __restrict__ out,
                                                int tid) {
    size_t base = (size_t)r * 64 * (F / 4);     // float4 offset of row-block
#pragma unroll
    for (int k = 0; k < 4; k++) {
        int idx = tid + k * 256;                // 0..1023 float4 in block
        float4 s0 = make_float4(0.f, 0.f, 0.f, 0.f);
        float4 s1 = make_float4(0.f, 0.f, 0.f, 0.f);
        float4 s2 = make_float4(0.f, 0.f, 0.f, 0.f);
        float4 s3 = make_float4(0.f, 0.f, 0.f, 0.f);
#pragma unroll
        for (int p = 0; p < 32; p += 4) {
            float4 v0 = ((const float4*)g_opart[p + 0])[base + idx];
            float4 v1 = ((const float4*)g_opart[p + 1])[base + idx];
            float4 v2 = ((const float4*)g_opart[p + 2])[base + idx];
            float4 v3 = ((const float4*)g_opart[p + 3])[base + idx];
            s0.x += v0.x; s0.y += v0.y; s0.z += v0.z; s0.w += v0.w;
            s1.x += v1.x; s1.y += v1.y; s1.z += v1.z; s1.w += v1.w;
            s2.x += v2.x; s2.y += v2.y; s2.z += v2.z; s2.w += v2.w;
            s3.x += v3.x; s3.y += v3.y; s3.z += v3.z; s3.w += v3.w;
        }
        int row = idx >> 4;                     // 16 float4 per row
        float inv = 1.0f / g_rowsum[r * 64 + row];
        float4 o;
        o.x = fmaxf(((s0.x + s1.x) + (s2.x + s3.x)) * inv, 0.f);
        o.y = fmaxf(((s0.y + s1.y) + (s2.y + s3.y)) * inv, 0.f);
        o.z = fmaxf(((s0.z + s1.z) + (s2.z + s3.z)) * inv, 0.f);
        o.w = fmaxf(((s0.w + s1.w) + (s2.w + s3.w)) * inv, 0.f);
        ((float4*)out)[base + idx] = o;
    }
}

// ---------------- K23sym: fused scores + exp + AV + tail reduction ----------
#define K23S_SMEM ((4096 * 4 + 64) * 4)   // his, njs, Pst1, Pst2, a = 64.3KB

__global__ __launch_bounds__(256, 2) void k23_sym(const int* __restrict__ adj,
                                                  const float* __restrict__ a,
                                                  float* __restrict__ out) {
    extern __shared__ float sm[];
    float* his  = sm;            // [64][64] rotated (i-tile h)
    float* njs  = sm + 4096;     // [64][64] rotated, negated (j-tile h)
    float* Pst1 = sm + 8192;     // [j][i] swizzled, mask adj[i,j]
    float* Pst2 = sm + 12288;    // [i][j] swizzled, mask adj[j,i]
    float* as_  = sm + 16384;    // [64]

    // triangular decode
    int t = blockIdx.x, ib = 0;
    while (t >= NT - ib) { t -= NT - ib; ib++; }
    int jb = ib + t;
    int gi0 = ib * 64, gj0 = jb * 64;
    bool diag = (ib == jb);

    int tid = threadIdx.x;
    int tx = tid & 15, ty = tid >> 4;
    int i0 = ty * 4, j0 = tx * 4;

    // ---- prefetch adjacency (both orientations), compress to bitmasks ----
    unsigned mij = 0, mji = 0;
#pragma unroll
    for (int k = 0; k < 4; k++) {
        int4 v = *(const int4*)&adj[(size_t)(gi0 + i0 + k) * N + gj0 + j0];
        unsigned b = (v.x > 0) | ((v.y > 0) << 1) | ((v.z > 0) << 2) | ((v.w > 0) << 3);
        mij |= b << (k * 4);     // bit (k*4+jj) = adj[gi0+i0+k][gj0+j0+jj]
    }
    if (!diag) {
#pragma unroll
        for (int jj = 0; jj < 4; jj++) {
            int4 v = *(const int4*)&adj[(size_t)(gj0 + j0 + jj) * N + gi0 + i0];
            unsigned b = (v.x > 0) | ((v.y > 0) << 1) | ((v.z > 0) << 2) | ((v.w > 0) << 3);
            mji |= b << (jj * 4);  // bit (jj*4+k) = adj[gj0+j0+jj][gi0+i0+k]
        }
    }

    // ---- stage his (rotated), njs (rotated + negated), a ----
    const float4* hgi = (const float4*)(g_h + (size_t)gi0 * F);
    const float4* hgj = (const float4*)(g_h + (size_t)gj0 * F);
#pragma unroll
    for (int u = 0; u < 4; u++) {
        int v = tid + u * 256;
        int r = v >> 4, c = v & 15;
        int cp = (c + (r >> 2)) & 15;
        *(float4*)&his[r * 64 + cp * 4] = hgi[v];
        float4 nv = hgj[v];
        nv.x = -nv.x; nv.y = -nv.y; nv.z = -nv.z; nv.w = -nv.w;
        *(float4*)&njs[r * 64 + cp * 4] = nv;
    }
    if (tid < 16) ((float4*)as_)[tid] = ((const float4*)a)[tid];
    __syncthreads();

    // ---- phase A: E tile, thread = 4i x 4j ----
    u64 accA[4][4] = {};
#pragma unroll
    for (int fc = 0; fc < 16; fc++) {
        ulonglong2 av = *(const ulonglong2*)&as_[fc * 4];
        int ci = ((fc + ty) & 15) * 4;
        int cj = ((fc + tx) & 15) * 4;
        ulonglong2 hr[4], nj[4];
#pragma unroll
        for (int k = 0; k < 4; k++) {
            hr[k] = *(const ulonglong2*)&his[(i0 + k) * 64 + ci];
            nj[k] = *(const ulonglong2*)&njs[(j0 + k) * 64 + cj];
        }
#pragma unroll
        for (int k = 0; k < 4; k++) {
#pragma unroll
            for (int jj = 0; jj < 4; jj++) {
                u64 d0 = f2add(hr[k].x, nj[jj].x) & ABS2MASK;
                accA[k][jj] = f2fma(d0, av.x, accA[k][jj]);
                u64 d1 = f2add(hr[k].y, nj[jj].y) & ABS2MASK;
                accA[k][jj] = f2fma(d1, av.y, accA[k][jj]);
            }
        }
    }

    // ---- exp once, mask twice, store Pst1 / Pst2 ----
    int swzA = (tx & 7) * 4;    // key for rows j0..j0+3  ((j>>2)&7 == tx&7)
    int swzB = (ty & 7) * 4;    // key for rows i0..i0+3
#pragma unroll
    for (int k = 0; k < 4; k++) {
        float e[4];
#pragma unroll
        for (int jj = 0; jj < 4; jj++)
            e[jj] = __expf(fmaxf(unpack_sum(accA[k][jj]), 0.f));
        int col = (i0 + k) ^ swzA;
        Pst1[(j0 + 0) * 64 + col] = (mij >> (k * 4 + 0)) & 1 ? e[0] : 0.f;
        Pst1[(j0 + 1) * 64 + col] = (mij >> (k * 4 + 1)) & 1 ? e[1] : 0.f;
        Pst1[(j0 + 2) * 64 + col] = (mij >> (k * 4 + 2)) & 1 ? e[2] : 0.f;
        Pst1[(j0 + 3) * 64 + col] = (mij >> (k * 4 + 3)) & 1 ? e[3] : 0.f;
        if (!diag) {
            float4 st;
            st.x = (mji >> (0 * 4 + k)) & 1 ? e[0] : 0.f;
            st.y = (mji >> (1 * 4 + k)) & 1 ? e[1] : 0.f;
            st.z = (mji >> (2 * 4 + k)) & 1 ? e[2] : 0.f;
            st.w = (mji >> (3 * 4 + k)) & 1 ? e[3] : 0.f;
            *(float4*)&Pst2[(i0 + k) * 64 + (j0 ^ swzB)] = st;
        }
    }
    __syncthreads();

    // ---- phase B1: O_i = sum_j P_ij * h_j (acc[f][i-pair]) ----
    {
        u64 acc[4][2] = {};          // [f][ipair]: lo=i0+2ip, hi=i0+2ip+1
        u64 rsa = 0, rsb = 0;        // packed rowsums (i0,i0+1), (i0+2,i0+3)
#pragma unroll 4
        for (int jq = 0; jq < 64; jq++) {
            int swz = ((jq >> 2) & 7) * 4;
            int cf = (((jq >> 2) + tx) & 15) * 4;
            ulonglong2 pp = *(const ulonglong2*)&Pst1[jq * 64 + (i0 ^ swz)];
            ulonglong2 hv = *(const ulonglong2*)&njs[jq * 64 + cf];
            rsa = f2add(rsa, pp.x);
            rsb = f2add(rsb, pp.y);
            float h0, h1, h2, h3;
            unpack2(hv.x, h0, h1); unpack2(hv.y, h2, h3);
            u64 H0 = dupf(h0), H1 = dupf(h1), H2 = dupf(h2), H3 = dupf(h3);
            acc[0][0] = f2fma(H0, pp.x, acc[0][0]);
            acc[0][1] = f2fma(H0, pp.y, acc[0][1]);
            acc[1][0] = f2fma(H1, pp.x, acc[1][0]);
            acc[1][1] = f2fma(H1, pp.y, acc[1][1]);
            acc[2][0] = f2fma(H2, pp.x, acc[2][0]);
            acc[2][1] = f2fma(H2, pp.y, acc[2][1]);
            acc[3][0] = f2fma(H3, pp.x, acc[3][0]);
            acc[3][1] = f2fma(H3, pp.y, acc[3][1]);
        }
        // identical rowsums across tx lanes -> tx==0 atomics only
        if (tx == 0) {
            float s0, s1, s2, s3;
            unpack2(rsa, s0, s1); unpack2(rsb, s2, s3);
            atomicAdd(&g_rowsum[gi0 + i0 + 0], s0);
            atomicAdd(&g_rowsum[gi0 + i0 + 1], s1);
            atomicAdd(&g_rowsum[gi0 + i0 + 2], s2);
            atomicAdd(&g_rowsum[gi0 + i0 + 3], s3);
        }
        // epilogue: gather transpose; njs held -h -> negate
        float v[4][4];   // [row r][f]
#pragma unroll
        for (int f = 0; f < 4; f++) {
            unpack2(acc[f][0], v[0][f], v[1][f]);
            unpack2(acc[f][1], v[2][f], v[3][f]);
        }
#pragma unroll
        for (int r = 0; r < 4; r++)
            *(float4*)&g_opart[jb][(size_t)(gi0 + i0 + r) * F + tx * 4] =
                make_float4(-v[r][0], -v[r][1], -v[r][2], -v[r][3]);
    }

    // ---- phase B2: O_j = sum_i P_ji * h_i ----
    if (!diag) {
        u64 acc[4][2] = {};
        u64 rsa = 0, rsb = 0;
#pragma unroll 4
        for (int iq = 0; iq < 64; iq++) {
            int swz = ((iq >> 2) & 7) * 4;
            int cf = (((iq >> 2) + tx) & 15) * 4;
            ulonglong2 pp = *(const ulonglong2*)&Pst2[iq * 64 + (i0 ^ swz)];
            ulonglong2 hv = *(const ulonglong2*)&his[iq * 64 + cf];
            rsa = f2add(rsa, pp.x);
            rsb = f2add(rsb, pp.y);
            float h0, h1, h2, h3;
            unpack2(hv.x, h0, h1); unpack2(hv.y, h2, h3);
            u64 H0 = dupf(h0), H1 = dupf(h1), H2 = dupf(h2), H3 = dupf(h3);
            acc[0][0] = f2fma(H0, pp.x, acc[0][0]);
            acc[0][1] = f2fma(H0, pp.y, acc[0][1]);
            acc[1][0] = f2fma(H1, pp.x, acc[1][0]);
            acc[1][1] = f2fma(H1, pp.y, acc[1][1]);
            acc[2][0] = f2fma(H2, pp.x, acc[2][0]);
            acc[2][1] = f2fma(H2, pp.y, acc[2][1]);
            acc[3][0] = f2fma(H3, pp.x, acc[3][0]);
            acc[3][1] = f2fma(H3, pp.y, acc[3][1]);
        }
        if (tx == 0) {
            float s0, s1, s2, s3;
            unpack2(rsa, s0, s1); unpack2(rsb, s2, s3);
            atomicAdd(&g_rowsum[gj0 + i0 + 0], s0);
            atomicAdd(&g_rowsum[gj0 + i0 + 1], s1);
            atomicAdd(&g_rowsum[gj0 + i0 + 2], s2);
            atomicAdd(&g_rowsum[gj0 + i0 + 3], s3);
        }
        float v[4][4];
#pragma unroll
        for (int f = 0; f < 4; f++) {
            unpack2(acc[f][0], v[0][f], v[1][f]);
            unpack2(acc[f][1], v[2][f], v[3][f]);
        }
#pragma unroll
        for (int r = 0; r < 4; r++)
            *(float4*)&g_opart[ib][(size_t)(gj0 + i0 + r) * F + tx * 4] =
                make_float4(v[r][0], v[r][1], v[r][2], v[r][3]);
    }

    // ---- completion counters; 32nd arriver reduces the row-block ----------
    __shared__ int s_doI, s_doJ;
    __threadfence();
    __syncthreads();
    if (tid == 0) {
        s_doI = (atomicAdd(&g_cnt[ib], 1) == 31);
        s_doJ = diag ? 0 : (atomicAdd(&g_cnt[jb], 1) == 31);
    }
    __syncthreads();
    if (s_doI) reduce_rowblock(ib, out, tid);
    if (s_doJ) reduce_rowblock(jb, out, tid);
}

// ---------------- launch ---------------------------------------------------
extern "C" void kernel_launch(void* const* d_in, const int* in_sizes, int n_in,
                              void* d_out, int out_size) {
    const float* x   = (const float*)d_in[0];
    const int*   adj = (const int*)  d_in[1];
    const float* W   = (const float*)d_in[2];
    const float* a   = (const float*)d_in[3];
    float*       out = (float*)d_out;

    cudaFuncSetAttribute(k23_sym, cudaFuncAttributeMaxDynamicSharedMemorySize, K23S_SMEM);

    dim3 g1(128, 4);
    k1_gemm_part<<<g1, 256>>>(x, W);
    k1b_reduce<<<128, 256>>>();
    k23_sym<<<NTRI, 256, K23S_SMEM>>>(adj, a, out);
}

// round 13
// speedup vs baseline: 1.3489x; 1.3489x over previous
#include <cuda_runtime.h>

#define N     2048
#define FIN   512
#define F     64
#define NT    32            // 64-row tiles per dimension
#define NTRI  528           // NT*(NT+1)/2
#define KSPL  8             // k1 split-K factor

typedef unsigned long long u64;

// ---------------- scratch (static device allocations only) ----------------
__device__ float g_hpart[KSPL][N * F];       // 4 MB: split-K partials of x@W
__device__ float g_h[N * F];                 // 512 KB
__device__ float g_rowsum[N];
__device__ float g_opart[NT][N * F];         // 16 MB: slot = other tile index

#define ABS2MASK 0x7FFFFFFF7FFFFFFFULL

__device__ __forceinline__ u64 f2add(u64 a, u64 b) {
    u64 r; asm("add.rn.f32x2 %0, %1, %2;" : "=l"(r) : "l"(a), "l"(b)); return r;
}
__device__ __forceinline__ u64 f2fma(u64 a, u64 b, u64 c) {
    u64 r; asm("fma.rn.f32x2 %0, %1, %2, %3;" : "=l"(r) : "l"(a), "l"(b), "l"(c)); return r;
}
__device__ __forceinline__ u64 dupf(float x) {
    u64 r; unsigned u = __float_as_uint(x);
    asm("mov.b64 %0, {%1,%1};" : "=l"(r) : "r"(u)); return r;
}
__device__ __forceinline__ float unpack_sum(u64 v) {
    float lo, hi;
    asm("mov.b64 {%0,%1}, %2;" : "=f"(lo), "=f"(hi) : "l"(v));
    return lo + hi;
}
__device__ __forceinline__ void unpack2(u64 v, float& lo, float& hi) {
    asm("mov.b64 {%0,%1}, %2;" : "=f"(lo), "=f"(hi) : "l"(v));
}

#define FMA4(a, s, v) { (a).x += (s)*(v).x; (a).y += (s)*(v).y; (a).z += (s)*(v).z; (a).w += (s)*(v).w; }

// ---------------- K1: split-K GEMM partials, 4r x 4c register micro ---------
// Block: 64 rows x 64 f, K-chunk 64 staged ONCE (one sync pair).
// Per k-group: 8 LDS.128 -> 64 FMAs. Grid (32, 8) = 256 blocks.
__global__ __launch_bounds__(256) void k1_gemm_part(const float* __restrict__ x,
                                                    const float* __restrict__ W) {
    __shared__ float xs[64][68];    // padded: row stride 68 kills ty conflicts
    __shared__ float ws[64][64];
    int tid = threadIdx.x;
    int r0 = blockIdx.x * 64;
    int kbase = blockIdx.y * 64;

    // stage xs [64 rows][64 k] and ws [64 k][64 f]
#pragma unroll
    for (int u = 0; u < 4; u++) {
        int v = tid + u * 256;
        int r = v >> 4, c = v & 15;
        *(float4*)&xs[r][c * 4] =
            *(const float4*)&x[(size_t)(r0 + r) * FIN + kbase + c * 4];
        *(float4*)&ws[r][c * 4] =
            *(const float4*)&W[(size_t)(kbase + r) * F + c * 4];
    }
    __syncthreads();

    int tx = tid & 15, ty = tid >> 4;
    int i0 = ty * 4;
    float4 acc[4];
#pragma unroll
    for (int r = 0; r < 4; r++) acc[r] = make_float4(0.f, 0.f, 0.f, 0.f);

#pragma unroll
    for (int kk = 0; kk < 16; kk++) {
        float4 xv0 = *(const float4*)&xs[i0 + 0][kk * 4];
        float4 xv1 = *(const float4*)&xs[i0 + 1][kk * 4];
        float4 xv2 = *(const float4*)&xs[i0 + 2][kk * 4];
        float4 xv3 = *(const float4*)&xs[i0 + 3][kk * 4];
        float4 w0 = ((const float4*)&ws[kk * 4 + 0][0])[tx];
        float4 w1 = ((const float4*)&ws[kk * 4 + 1][0])[tx];
        float4 w2 = ((const float4*)&ws[kk * 4 + 2][0])[tx];
        float4 w3 = ((const float4*)&ws[kk * 4 + 3][0])[tx];
        FMA4(acc[0], xv0.x, w0); FMA4(acc[0], xv0.y, w1);
        FMA4(acc[0], xv0.z, w2); FMA4(acc[0], xv0.w, w3);
        FMA4(acc[1], xv1.x, w0); FMA4(acc[1], xv1.y, w1);
        FMA4(acc[1], xv1.z, w2); FMA4(acc[1], xv1.w, w3);
        FMA4(acc[2], xv2.x, w0); FMA4(acc[2], xv2.y, w1);
        FMA4(acc[2], xv2.z, w2); FMA4(acc[2], xv2.w, w3);
        FMA4(acc[3], xv3.x, w0); FMA4(acc[3], xv3.y, w1);
        FMA4(acc[3], xv3.z, w2); FMA4(acc[3], xv3.w, w3);
    }
#pragma unroll
    for (int r = 0; r < 4; r++)
        *(float4*)&g_hpart[blockIdx.y][(size_t)(r0 + i0 + r) * F + tx * 4] = acc[r];
}

// ---------------- K1b: g_h = sum of 8 partials; zero rowsum ----------------
__global__ __launch_bounds__(256) void k1b_reduce() {
    int idx = blockIdx.x * 256 + threadIdx.x;   // 128 x 256 = 32768 float4s
    float4 s0 = make_float4(0.f, 0.f, 0.f, 0.f);
    float4 s1 = make_float4(0.f, 0.f, 0.f, 0.f);
#pragma unroll
    for (int p = 0; p < KSPL; p += 2) {
        float4 a0 = ((const float4*)g_hpart[p + 0])[idx];
        float4 a1 = ((const float4*)g_hpart[p + 1])[idx];
        s0.x += a0.x; s0.y += a0.y; s0.z += a0.z; s0.w += a0.w;
        s1.x += a1.x; s1.y += a1.y; s1.z += a1.z; s1.w += a1.w;
    }
    float4 r;
    r.x = s0.x + s1.x; r.y = s0.y + s1.y;
    r.z = s0.z + s1.z; r.w = s0.w + s1.w;
    ((float4*)g_h)[idx] = r;
    if (idx < N) g_rowsum[idx] = 0.0f;
}

// ---------------- K23sym (exact R11 structure, best measured) ---------------
#define K23S_SMEM ((4096 * 4 + 64) * 4)   // his, njs, Pst1, Pst2, a = 64.3KB

__global__ __launch_bounds__(256, 2) void k23_sym(const int* __restrict__ adj,
                                                  const float* __restrict__ a) {
    extern __shared__ float sm[];
    float* his  = sm;            // [64][64] rotated (i-tile h)
    float* njs  = sm + 4096;     // [64][64] rotated, negated (j-tile h)
    float* Pst1 = sm + 8192;     // [j][i] swizzled, mask adj[i,j]
    float* Pst2 = sm + 12288;    // [i][j] swizzled, mask adj[j,i]
    float* as_  = sm + 16384;    // [64]

    // triangular decode
    int t = blockIdx.x, ib = 0;
    while (t >= NT - ib) { t -= NT - ib; ib++; }
    int jb = ib + t;
    int gi0 = ib * 64, gj0 = jb * 64;
    bool diag = (ib == jb);

    int tid = threadIdx.x;
    int tx = tid & 15, ty = tid >> 4;
    int i0 = ty * 4, j0 = tx * 4;

    // ---- prefetch adjacency (both orientations), compress to bitmasks ----
    unsigned mij = 0, mji = 0;
#pragma unroll
    for (int k = 0; k < 4; k++) {
        int4 v = *(const int4*)&adj[(size_t)(gi0 + i0 + k) * N + gj0 + j0];
        unsigned b = (v.x > 0) | ((v.y > 0) << 1) | ((v.z > 0) << 2) | ((v.w > 0) << 3);
        mij |= b << (k * 4);
    }
    if (!diag) {
#pragma unroll
        for (int jj = 0; jj < 4; jj++) {
            int4 v = *(const int4*)&adj[(size_t)(gj0 + j0 + jj) * N + gi0 + i0];
            unsigned b = (v.x > 0) | ((v.y > 0) << 1) | ((v.z > 0) << 2) | ((v.w > 0) << 3);
            mji |= b << (jj * 4);
        }
    }

    // ---- stage his (rotated), njs (rotated + negated), a ----
    const float4* hgi = (const float4*)(g_h + (size_t)gi0 * F);
    const float4* hgj = (const float4*)(g_h + (size_t)gj0 * F);
#pragma unroll
    for (int u = 0; u < 4; u++) {
        int v = tid + u * 256;
        int r = v >> 4, c = v & 15;
        int cp = (c + (r >> 2)) & 15;
        *(float4*)&his[r * 64 + cp * 4] = hgi[v];
        float4 nv = hgj[v];
        nv.x = -nv.x; nv.y = -nv.y; nv.z = -nv.z; nv.w = -nv.w;
        *(float4*)&njs[r * 64 + cp * 4] = nv;
    }
    if (tid < 16) ((float4*)as_)[tid] = ((const float4*)a)[tid];
    __syncthreads();

    // ---- phase A: E tile, thread = 4i x 4j ----
    u64 accA[4][4] = {};
#pragma unroll
    for (int fc = 0; fc < 16; fc++) {
        ulonglong2 av = *(const ulonglong2*)&as_[fc * 4];
        int ci = ((fc + ty) & 15) * 4;
        int cj = ((fc + tx) & 15) * 4;
        ulonglong2 hr[4], nj[4];
#pragma unroll
        for (int k = 0; k < 4; k++) {
            hr[k] = *(const ulonglong2*)&his[(i0 + k) * 64 + ci];
            nj[k] = *(const ulonglong2*)&njs[(j0 + k) * 64 + cj];
        }
#pragma unroll
        for (int k = 0; k < 4; k++) {
#pragma unroll
            for (int jj = 0; jj < 4; jj++) {
                u64 d0 = f2add(hr[k].x, nj[jj].x) & ABS2MASK;
                accA[k][jj] = f2fma(d0, av.x, accA[k][jj]);
                u64 d1 = f2add(hr[k].y, nj[jj].y) & ABS2MASK;
                accA[k][jj] = f2fma(d1, av.y, accA[k][jj]);
            }
        }
    }

    // ---- exp once, mask twice, store Pst1 / Pst2 ----
    int swzA = (tx & 7) * 4;
    int swzB = (ty & 7) * 4;
#pragma unroll
    for (int k = 0; k < 4; k++) {
        float e[4];
#pragma unroll
        for (int jj = 0; jj < 4; jj++)
            e[jj] = __expf(fmaxf(unpack_sum(accA[k][jj]), 0.f));
        int col = (i0 + k) ^ swzA;
        Pst1[(j0 + 0) * 64 + col] = (mij >> (k * 4 + 0)) & 1 ? e[0] : 0.f;
        Pst1[(j0 + 1) * 64 + col] = (mij >> (k * 4 + 1)) & 1 ? e[1] : 0.f;
        Pst1[(j0 + 2) * 64 + col] = (mij >> (k * 4 + 2)) & 1 ? e[2] : 0.f;
        Pst1[(j0 + 3) * 64 + col] = (mij >> (k * 4 + 3)) & 1 ? e[3] : 0.f;
        if (!diag) {
            float4 st;
            st.x = (mji >> (0 * 4 + k)) & 1 ? e[0] : 0.f;
            st.y = (mji >> (1 * 4 + k)) & 1 ? e[1] : 0.f;
            st.z = (mji >> (2 * 4 + k)) & 1 ? e[2] : 0.f;
            st.w = (mji >> (3 * 4 + k)) & 1 ? e[3] : 0.f;
            *(float4*)&Pst2[(i0 + k) * 64 + (j0 ^ swzB)] = st;
        }
    }
    __syncthreads();

    // ---- phase B1: O_i = sum_j P_ij * h_j (acc[f][i-pair]) ----
    {
        u64 acc[4][2] = {};
        u64 rsa = 0, rsb = 0;
#pragma unroll 4
        for (int jq = 0; jq < 64; jq++) {
            int swz = ((jq >> 2) & 7) * 4;
            int cf = (((jq >> 2) + tx) & 15) * 4;
            ulonglong2 pp = *(const ulonglong2*)&Pst1[jq * 64 + (i0 ^ swz)];
            ulonglong2 hv = *(const ulonglong2*)&njs[jq * 64 + cf];
            rsa = f2add(rsa, pp.x);
            rsb = f2add(rsb, pp.y);
            float h0, h1, h2, h3;
            unpack2(hv.x, h0, h1); unpack2(hv.y, h2, h3);
            u64 H0 = dupf(h0), H1 = dupf(h1), H2 = dupf(h2), H3 = dupf(h3);
            acc[0][0] = f2fma(H0, pp.x, acc[0][0]);
            acc[0][1] = f2fma(H0, pp.y, acc[0][1]);
            acc[1][0] = f2fma(H1, pp.x, acc[1][0]);
            acc[1][1] = f2fma(H1, pp.y, acc[1][1]);
            acc[2][0] = f2fma(H2, pp.x, acc[2][0]);
            acc[2][1] = f2fma(H2, pp.y, acc[2][1]);
            acc[3][0] = f2fma(H3, pp.x, acc[3][0]);
            acc[3][1] = f2fma(H3, pp.y, acc[3][1]);
        }
        if (tx == 0) {
            float s0, s1, s2, s3;
            unpack2(rsa, s0, s1); unpack2(rsb, s2, s3);
            atomicAdd(&g_rowsum[gi0 + i0 + 0], s0);
            atomicAdd(&g_rowsum[gi0 + i0 + 1], s1);
            atomicAdd(&g_rowsum[gi0 + i0 + 2], s2);
            atomicAdd(&g_rowsum[gi0 + i0 + 3], s3);
        }
        float v[4][4];
#pragma unroll
        for (int f = 0; f < 4; f++) {
            unpack2(acc[f][0], v[0][f], v[1][f]);
            unpack2(acc[f][1], v[2][f], v[3][f]);
        }
#pragma unroll
        for (int r = 0; r < 4; r++)
            *(float4*)&g_opart[jb][(size_t)(gi0 + i0 + r) * F + tx * 4] =
                make_float4(-v[r][0], -v[r][1], -v[r][2], -v[r][3]);
    }

    // ---- phase B2: O_j = sum_i P_ji * h_i ----
    if (!diag) {
        u64 acc[4][2] = {};
        u64 rsa = 0, rsb = 0;
#pragma unroll 4
        for (int iq = 0; iq < 64; iq++) {
            int swz = ((iq >> 2) & 7) * 4;
            int cf = (((iq >> 2) + tx) & 15) * 4;
            ulonglong2 pp = *(const ulonglong2*)&Pst2[iq * 64 + (i0 ^ swz)];
            ulonglong2 hv = *(const ulonglong2*)&his[iq * 64 + cf];
            rsa = f2add(rsa, pp.x);
            rsb = f2add(rsb, pp.y);
            float h0, h1, h2, h3;
            unpack2(hv.x, h0, h1); unpack2(hv.y, h2, h3);
            u64 H0 = dupf(h0), H1 = dupf(h1), H2 = dupf(h2), H3 = dupf(h3);
            acc[0][0] = f2fma(H0, pp.x, acc[0][0]);
            acc[0][1] = f2fma(H0, pp.y, acc[0][1]);
            acc[1][0] = f2fma(H1, pp.x, acc[1][0]);
            acc[1][1] = f2fma(H1, pp.y, acc[1][1]);
            acc[2][0] = f2fma(H2, pp.x, acc[2][0]);
            acc[2][1] = f2fma(H2, pp.y, acc[2][1]);
            acc[3][0] = f2fma(H3, pp.x, acc[3][0]);
            acc[3][1] = f2fma(H3, pp.y, acc[3][1]);
        }
        if (tx == 0) {
            float s0, s1, s2, s3;
            unpack2(rsa, s0, s1); unpack2(rsb, s2, s3);
            atomicAdd(&g_rowsum[gj0 + i0 + 0], s0);
            atomicAdd(&g_rowsum[gj0 + i0 + 1], s1);
            atomicAdd(&g_rowsum[gj0 + i0 + 2], s2);
            atomicAdd(&g_rowsum[gj0 + i0 + 3], s3);
        }
        float v[4][4];
#pragma unroll
        for (int f = 0; f < 4; f++) {
            unpack2(acc[f][0], v[0][f], v[1][f]);
            unpack2(acc[f][1], v[2][f], v[3][f]);
        }
#pragma unroll
        for (int r = 0; r < 4; r++)
            *(float4*)&g_opart[ib][(size_t)(gj0 + i0 + r) * F + tx * 4] =
                make_float4(v[r][0], v[r][1], v[r][2], v[r][3]);
    }
}

// ---------------- K4: out = relu((sum of 32 partials) / rowsum) ------------
__global__ __launch_bounds__(256) void k4_final(float* __restrict__ out) {
    int idx = blockIdx.x * 256 + threadIdx.x;          // 0 .. N*F-1
    float inv = 1.0f / g_rowsum[idx >> 6];
    float s0 = 0.f, s1 = 0.f, s2 = 0.f, s3 = 0.f;
#pragma unroll
    for (int b = 0; b < 2; b++) {
        float v[16];
#pragma unroll
        for (int p = 0; p < 16; p++) v[p] = g_opart[b * 16 + p][idx];
#pragma unroll
        for (int p = 0; p < 16; p += 4) {
            s0 += v[p + 0]; s1 += v[p + 1]; s2 += v[p + 2]; s3 += v[p + 3];
        }
    }
    out[idx] = fmaxf(((s0 + s1) + (s2 + s3)) * inv, 0.f);
}

// ---------------- launch ---------------------------------------------------
extern "C" void kernel_launch(void* const* d_in, const int* in_sizes, int n_in,
                              void* d_out, int out_size) {
    const float* x   = (const float*)d_in[0];
    const int*   adj = (const int*)  d_in[1];
    const float* W   = (const float*)d_in[2];
    const float* a   = (const float*)d_in[3];
    float*       out = (float*)d_out;

    cudaFuncSetAttribute(k23_sym, cudaFuncAttributeMaxDynamicSharedMemorySize, K23S_SMEM);

    dim3 g1(32, KSPL);
    k1_gemm_part<<<g1, 256>>>(x, W);
    k1b_reduce<<<128, 256>>>();
    k23_sym<<<NTRI, 256, K23S_SMEM>>>(adj, a);
    k4_final<<<N * F / 256, 256>>>(out);
}

// round 14
// speedup vs baseline: 1.3559x; 1.0052x over previous
#include <cuda_runtime.h>

#define N     2048
#define FIN   512
#define F     64
#define NT    32            // 64-row tiles per dimension
#define NTRI  528           // NT*(NT+1)/2
#define KSPL  8             // k1 split-K factor

typedef unsigned long long u64;

// ---------------- scratch (static device allocations only) ----------------
__device__ float g_hpart[KSPL][N * F];       // 4 MB: split-K partials of x@W
__device__ float g_h[N * F];                 // 512 KB
__device__ float g_rowsum[N];
__device__ float g_opart[NT][N * F];         // 16 MB: slot = other tile index

#define ABS2MASK 0x7FFFFFFF7FFFFFFFULL

__device__ __forceinline__ u64 f2add(u64 a, u64 b) {
    u64 r; asm("add.rn.f32x2 %0, %1, %2;" : "=l"(r) : "l"(a), "l"(b)); return r;
}
__device__ __forceinline__ u64 f2fma(u64 a, u64 b, u64 c) {
    u64 r; asm("fma.rn.f32x2 %0, %1, %2, %3;" : "=l"(r) : "l"(a), "l"(b), "l"(c)); return r;
}
__device__ __forceinline__ u64 dupf(float x) {
    u64 r; unsigned u = __float_as_uint(x);
    asm("mov.b64 %0, {%1,%1};" : "=l"(r) : "r"(u)); return r;
}
__device__ __forceinline__ float unpack_sum(u64 v) {
    float lo, hi;
    asm("mov.b64 {%0,%1}, %2;" : "=f"(lo), "=f"(hi) : "l"(v));
    return lo + hi;
}
__device__ __forceinline__ void unpack2(u64 v, float& lo, float& hi) {
    asm("mov.b64 {%0,%1}, %2;" : "=f"(lo), "=f"(hi) : "l"(v));
}

#define FMA4(a, s, v) { (a).x += (s)*(v).x; (a).y += (s)*(v).y; (a).z += (s)*(v).z; (a).w += (s)*(v).w; }

// ---------------- K1: split-K GEMM partials, 4r x 4c register micro ---------
__global__ __launch_bounds__(256) void k1_gemm_part(const float* __restrict__ x,
                                                    const float* __restrict__ W) {
    __shared__ float xs[64][68];    // padded: row stride 68 kills ty conflicts
    __shared__ float ws[64][64];
    int tid = threadIdx.x;
    int r0 = blockIdx.x * 64;
    int kbase = blockIdx.y * 64;

    // stage xs [64 rows][64 k] and ws [64 k][64 f]
#pragma unroll
    for (int u = 0; u < 4; u++) {
        int v = tid + u * 256;
        int r = v >> 4, c = v & 15;
        *(float4*)&xs[r][c * 4] =
            *(const float4*)&x[(size_t)(r0 + r) * FIN + kbase + c * 4];
        *(float4*)&ws[r][c * 4] =
            *(const float4*)&W[(size_t)(kbase + r) * F + c * 4];
    }
    __syncthreads();

    int tx = tid & 15, ty = tid >> 4;
    int i0 = ty * 4;
    float4 acc[4];
#pragma unroll
    for (int r = 0; r < 4; r++) acc[r] = make_float4(0.f, 0.f, 0.f, 0.f);

#pragma unroll
    for (int kk = 0; kk < 16; kk++) {
        float4 xv0 = *(const float4*)&xs[i0 + 0][kk * 4];
        float4 xv1 = *(const float4*)&xs[i0 + 1][kk * 4];
        float4 xv2 = *(const float4*)&xs[i0 + 2][kk * 4];
        float4 xv3 = *(const float4*)&xs[i0 + 3][kk * 4];
        float4 w0 = ((const float4*)&ws[kk * 4 + 0][0])[tx];
        float4 w1 = ((const float4*)&ws[kk * 4 + 1][0])[tx];
        float4 w2 = ((const float4*)&ws[kk * 4 + 2][0])[tx];
        float4 w3 = ((const float4*)&ws[kk * 4 + 3][0])[tx];
        FMA4(acc[0], xv0.x, w0); FMA4(acc[0], xv0.y, w1);
        FMA4(acc[0], xv0.z, w2); FMA4(acc[0], xv0.w, w3);
        FMA4(acc[1], xv1.x, w0); FMA4(acc[1], xv1.y, w1);
        FMA4(acc[1], xv1.z, w2); FMA4(acc[1], xv1.w, w3);
        FMA4(acc[2], xv2.x, w0); FMA4(acc[2], xv2.y, w1);
        FMA4(acc[2], xv2.z, w2); FMA4(acc[2], xv2.w, w3);
        FMA4(acc[3], xv3.x, w0); FMA4(acc[3], xv3.y, w1);
        FMA4(acc[3], xv3.z, w2); FMA4(acc[3], xv3.w, w3);
    }
#pragma unroll
    for (int r = 0; r < 4; r++)
        *(float4*)&g_hpart[blockIdx.y][(size_t)(r0 + i0 + r) * F + tx * 4] = acc[r];
}

// ---------------- K1b: g_h = sum of 8 partials; zero rowsum ----------------
__global__ __launch_bounds__(256) void k1b_reduce() {
    int idx = blockIdx.x * 256 + threadIdx.x;   // 128 x 256 = 32768 float4s
    float4 s0 = make_float4(0.f, 0.f, 0.f, 0.f);
    float4 s1 = make_float4(0.f, 0.f, 0.f, 0.f);
#pragma unroll
    for (int p = 0; p < KSPL; p += 2) {
        float4 a0 = ((const float4*)g_hpart[p + 0])[idx];
        float4 a1 = ((const float4*)g_hpart[p + 1])[idx];
        s0.x += a0.x; s0.y += a0.y; s0.z += a0.z; s0.w += a0.w;
        s1.x += a1.x; s1.y += a1.y; s1.z += a1.z; s1.w += a1.w;
    }
    float4 r;
    r.x = s0.x + s1.x; r.y = s0.y + s1.y;
    r.z = s0.z + s1.z; r.w = s0.w + s1.w;
    ((float4*)g_h)[idx] = r;
    if (idx < N) g_rowsum[idx] = 0.0f;
}

// ---------------- K23sym: occ 3 (smem 64.3KB x3 = 193KB <= 228KB) -----------
// Phase A restructured: hr loaded per-k (1 live vector) to fit the 85-reg cap.
#define K23S_SMEM ((4096 * 4 + 64) * 4)   // his, njs, Pst1, Pst2, a = 64.3KB

__global__ __launch_bounds__(256, 3) void k23_sym(const int* __restrict__ adj,
                                                  const float* __restrict__ a) {
    extern __shared__ float sm[];
    float* his  = sm;            // [64][64] rotated (i-tile h)
    float* njs  = sm + 4096;     // [64][64] rotated, negated (j-tile h)
    float* Pst1 = sm + 8192;     // [j][i] swizzled, mask adj[i,j]
    float* Pst2 = sm + 12288;    // [i][j] swizzled, mask adj[j,i]
    float* as_  = sm + 16384;    // [64]

    // triangular decode
    int t = blockIdx.x, ib = 0;
    while (t >= NT - ib) { t -= NT - ib; ib++; }
    int jb = ib + t;
    int gi0 = ib * 64, gj0 = jb * 64;
    bool diag = (ib == jb);

    int tid = threadIdx.x;
    int tx = tid & 15, ty = tid >> 4;
    int i0 = ty * 4, j0 = tx * 4;

    // ---- prefetch adjacency (both orientations), compress to bitmasks ----
    unsigned mij = 0, mji = 0;
#pragma unroll
    for (int k = 0; k < 4; k++) {
        int4 v = *(const int4*)&adj[(size_t)(gi0 + i0 + k) * N + gj0 + j0];
        unsigned b = (v.x > 0) | ((v.y > 0) << 1) | ((v.z > 0) << 2) | ((v.w > 0) << 3);
        mij |= b << (k * 4);
    }
    if (!diag) {
#pragma unroll
        for (int jj = 0; jj < 4; jj++) {
            int4 v = *(const int4*)&adj[(size_t)(gj0 + j0 + jj) * N + gi0 + i0];
            unsigned b = (v.x > 0) | ((v.y > 0) << 1) | ((v.z > 0) << 2) | ((v.w > 0) << 3);
            mji |= b << (jj * 4);
        }
    }

    // ---- stage his (rotated), njs (rotated + negated), a ----
    const float4* hgi = (const float4*)(g_h + (size_t)gi0 * F);
    const float4* hgj = (const float4*)(g_h + (size_t)gj0 * F);
#pragma unroll
    for (int u = 0; u < 4; u++) {
        int v = tid + u * 256;
        int r = v >> 4, c = v & 15;
        int cp = (c + (r >> 2)) & 15;
        *(float4*)&his[r * 64 + cp * 4] = hgi[v];
        float4 nv = hgj[v];
        nv.x = -nv.x; nv.y = -nv.y; nv.z = -nv.z; nv.w = -nv.w;
        *(float4*)&njs[r * 64 + cp * 4] = nv;
    }
    if (tid < 16) ((float4*)as_)[tid] = ((const float4*)a)[tid];
    __syncthreads();

    // ---- phase A: E tile, thread = 4i x 4j; hr loaded per-k (reg saver) ----
    u64 accA[4][4] = {};
#pragma unroll
    for (int fc = 0; fc < 16; fc++) {
        ulonglong2 av = *(const ulonglong2*)&as_[fc * 4];
        int ci = ((fc + ty) & 15) * 4;
        int cj = ((fc + tx) & 15) * 4;
        ulonglong2 nj[4];
#pragma unroll
        for (int jj = 0; jj < 4; jj++)
            nj[jj] = *(const ulonglong2*)&njs[(j0 + jj) * 64 + cj];
#pragma unroll
        for (int k = 0; k < 4; k++) {
            ulonglong2 hr = *(const ulonglong2*)&his[(i0 + k) * 64 + ci];
#pragma unroll
            for (int jj = 0; jj < 4; jj++) {
                u64 d0 = f2add(hr.x, nj[jj].x) & ABS2MASK;
                accA[k][jj] = f2fma(d0, av.x, accA[k][jj]);
                u64 d1 = f2add(hr.y, nj[jj].y) & ABS2MASK;
                accA[k][jj] = f2fma(d1, av.y, accA[k][jj]);
            }
        }
    }

    // ---- exp once, mask twice, store Pst1 / Pst2 ----
    int swzA = (tx & 7) * 4;
    int swzB = (ty & 7) * 4;
#pragma unroll
    for (int k = 0; k < 4; k++) {
        float e[4];
#pragma unroll
        for (int jj = 0; jj < 4; jj++)
            e[jj] = __expf(fmaxf(unpack_sum(accA[k][jj]), 0.f));
        int col = (i0 + k) ^ swzA;
        Pst1[(j0 + 0) * 64 + col] = (mij >> (k * 4 + 0)) & 1 ? e[0] : 0.f;
        Pst1[(j0 + 1) * 64 + col] = (mij >> (k * 4 + 1)) & 1 ? e[1] : 0.f;
        Pst1[(j0 + 2) * 64 + col] = (mij >> (k * 4 + 2)) & 1 ? e[2] : 0.f;
        Pst1[(j0 + 3) * 64 + col] = (mij >> (k * 4 + 3)) & 1 ? e[3] : 0.f;
        if (!diag) {
            float4 st;
            st.x = (mji >> (0 * 4 + k)) & 1 ? e[0] : 0.f;
            st.y = (mji >> (1 * 4 + k)) & 1 ? e[1] : 0.f;
            st.z = (mji >> (2 * 4 + k)) & 1 ? e[2] : 0.f;
            st.w = (mji >> (3 * 4 + k)) & 1 ? e[3] : 0.f;
            *(float4*)&Pst2[(i0 + k) * 64 + (j0 ^ swzB)] = st;
        }
    }
    __syncthreads();

    // ---- phase B1: O_i = sum_j P_ij * h_j (acc[f][i-pair]) ----
    {
        u64 acc[4][2] = {};
        u64 rsa = 0, rsb = 0;
#pragma unroll 4
        for (int jq = 0; jq < 64; jq++) {
            int swz = ((jq >> 2) & 7) * 4;
            int cf = (((jq >> 2) + tx) & 15) * 4;
            ulonglong2 pp = *(const ulonglong2*)&Pst1[jq * 64 + (i0 ^ swz)];
            ulonglong2 hv = *(const ulonglong2*)&njs[jq * 64 + cf];
            rsa = f2add(rsa, pp.x);
            rsb = f2add(rsb, pp.y);
            float h0, h1, h2, h3;
            unpack2(hv.x, h0, h1); unpack2(hv.y, h2, h3);
            u64 H0 = dupf(h0), H1 = dupf(h1), H2 = dupf(h2), H3 = dupf(h3);
            acc[0][0] = f2fma(H0, pp.x, acc[0][0]);
            acc[0][1] = f2fma(H0, pp.y, acc[0][1]);
            acc[1][0] = f2fma(H1, pp.x, acc[1][0]);
            acc[1][1] = f2fma(H1, pp.y, acc[1][1]);
            acc[2][0] = f2fma(H2, pp.x, acc[2][0]);
            acc[2][1] = f2fma(H2, pp.y, acc[2][1]);
            acc[3][0] = f2fma(H3, pp.x, acc[3][0]);
            acc[3][1] = f2fma(H3, pp.y, acc[3][1]);
        }
        if (tx == 0) {
            float s0, s1, s2, s3;
            unpack2(rsa, s0, s1); unpack2(rsb, s2, s3);
            atomicAdd(&g_rowsum[gi0 + i0 + 0], s0);
            atomicAdd(&g_rowsum[gi0 + i0 + 1], s1);
            atomicAdd(&g_rowsum[gi0 + i0 + 2], s2);
            atomicAdd(&g_rowsum[gi0 + i0 + 3], s3);
        }
        float v[4][4];
#pragma unroll
        for (int f = 0; f < 4; f++) {
            unpack2(acc[f][0], v[0][f], v[1][f]);
            unpack2(acc[f][1], v[2][f], v[3][f]);
        }
#pragma unroll
        for (int r = 0; r < 4; r++)
            *(float4*)&g_opart[jb][(size_t)(gi0 + i0 + r) * F + tx * 4] =
                make_float4(-v[r][0], -v[r][1], -v[r][2], -v[r][3]);
    }

    // ---- phase B2: O_j = sum_i P_ji * h_i ----
    if (!diag) {
        u64 acc[4][2] = {};
        u64 rsa = 0, rsb = 0;
#pragma unroll 4
        for (int iq = 0; iq < 64; iq++) {
            int swz = ((iq >> 2) & 7) * 4;
            int cf = (((iq >> 2) + tx) & 15) * 4;
            ulonglong2 pp = *(const ulonglong2*)&Pst2[iq * 64 + (i0 ^ swz)];
            ulonglong2 hv = *(const ulonglong2*)&his[iq * 64 + cf];
            rsa = f2add(rsa, pp.x);
            rsb = f2add(rsb, pp.y);
            float h0, h1, h2, h3;
            unpack2(hv.x, h0, h1); unpack2(hv.y, h2, h3);
            u64 H0 = dupf(h0), H1 = dupf(h1), H2 = dupf(h2), H3 = dupf(h3);
            acc[0][0] = f2fma(H0, pp.x, acc[0][0]);
            acc[0][1] = f2fma(H0, pp.y, acc[0][1]);
            acc[1][0] = f2fma(H1, pp.x, acc[1][0]);
            acc[1][1] = f2fma(H1, pp.y, acc[1][1]);
            acc[2][0] = f2fma(H2, pp.x, acc[2][0]);
            acc[2][1] = f2fma(H2, pp.y, acc[2][1]);
            acc[3][0] = f2fma(H3, pp.x, acc[3][0]);
            acc[3][1] = f2fma(H3, pp.y, acc[3][1]);
        }
        if (tx == 0) {
            float s0, s1, s2, s3;
            unpack2(rsa, s0, s1); unpack2(rsb, s2, s3);
            atomicAdd(&g_rowsum[gj0 + i0 + 0], s0);
            atomicAdd(&g_rowsum[gj0 + i0 + 1], s1);
            atomicAdd(&g_rowsum[gj0 + i0 + 2], s2);
            atomicAdd(&g_rowsum[gj0 + i0 + 3], s3);
        }
        float v[4][4];
#pragma unroll
        for (int f = 0; f < 4; f++) {
            unpack2(acc[f][0], v[0][f], v[1][f]);
            unpack2(acc[f][1], v[2][f], v[3][f]);
        }
#pragma unroll
        for (int r = 0; r < 4; r++)
            *(float4*)&g_opart[ib][(size_t)(gj0 + i0 + r) * F + tx * 4] =
                make_float4(v[r][0], v[r][1], v[r][2], v[r][3]);
    }
}

// ---------------- K4: out = relu((sum of 32 partials) / rowsum) ------------
// Flat 32-way MLP; 1024 blocks x 128 threads for fine SM balance.
__global__ __launch_bounds__(128) void k4_final(float* __restrict__ out) {
    int idx = blockIdx.x * 128 + threadIdx.x;          // 0 .. N*F-1
    float inv = 1.0f / g_rowsum[idx >> 6];
    float v[32];
#pragma unroll
    for (int p = 0; p < 32; p++) v[p] = g_opart[p][idx];
    float s0 = 0.f, s1 = 0.f, s2 = 0.f, s3 = 0.f;
#pragma unroll
    for (int p = 0; p < 32; p += 4) {
        s0 += v[p + 0]; s1 += v[p + 1]; s2 += v[p + 2]; s3 += v[p + 3];
    }
    out[idx] = fmaxf(((s0 + s1) + (s2 + s3)) * inv, 0.f);
}

// ---------------- launch ---------------------------------------------------
extern "C" void kernel_launch(void* const* d_in, const int* in_sizes, int n_in,
                              void* d_out, int out_size) {
    const float* x   = (const float*)d_in[0];
    const int*   adj = (const int*)  d_in[1];
    const float* W   = (const float*)d_in[2];
    const float* a   = (const float*)d_in[3];
    float*       out = (float*)d_out;

    cudaFuncSetAttribute(k23_sym, cudaFuncAttributeMaxDynamicSharedMemorySize, K23S_SMEM);

    dim3 g1(32, KSPL);
    k1_gemm_part<<<g1, 256>>>(x, W);
    k1b_reduce<<<128, 256>>>();
    k23_sym<<<NTRI, 256, K23S_SMEM>>>(adj, a);
    k4_final<<<N * F / 128, 128>>>(out);
}